// round 15
// baseline (speedup 1.0000x reference)
#include <cuda_runtime.h>
#include <cuda_fp16.h>
#include <cstdint>

// ---------------------------------------------------------------------------
// Round 15: R14 + (1) full-width L2 banding (B weight panels L2-resident, A
// streamed once) and (2) 2-stage attention pipeline (92KB smem -> 2 CTAs/SM).
// ---------------------------------------------------------------------------

#define NTOK 16384
#define CDIM 1024
#define HEADS 16
#define HDIM 64
#define WS 512
#define SHIFTK 256
#define MVD4 4096
#define KCAT 9216
#define HID 4096
#define NZ 512

// fp32 buffers
__device__ float g_x1    [(long)NTOK * CDIM];
__device__ float g_x2    [(long)NTOK * CDIM];
// fp16 buffers
__device__ __half g_qkvh [(long)NTOK * 3 * CDIM];
__device__ __half g_qkvwT[(long)3 * CDIM * CDIM];
__device__ __half g_projwT[(long)CDIM * CDIM];
__device__ __half g_mv1T [(long)HID * KCAT];
__device__ __half g_mv2T [(long)CDIM * HID];
__device__ __half g_mlp1T[(long)HID * CDIM];
__device__ __half g_mlp2T[(long)CDIM * HID];
__device__ __half g_mvnh [(long)NTOK * MVD4];
__device__ __half g_mvch [(long)NTOK * MVD4];
__device__ __half g_lnxh [(long)NTOK * CDIM];
__device__ __half g_lnbh [(long)NTOK * CDIM];
__device__ __half g_h1h  [(long)NTOK * HID];
__device__ __half g_attnh[(long)NTOK * CDIM];

// ======================= helpers =======================
__device__ __forceinline__ uint32_t smem_u32(const void* p) {
    uint32_t a;
    asm("{ .reg .u64 t; cvta.to.shared.u64 t, %1; cvt.u32.u64 %0, t; }"
        : "=r"(a) : "l"(p));
    return a;
}
__device__ __forceinline__ float gelu_tanh(float v) {
    return 0.5f * v * (1.f + tanhf(0.7978845608028654f * (v + 0.044715f * v * v * v)));
}
__device__ __forceinline__ unsigned h2(float a, float b) {
    __half2 h = __floats2half2_rn(a, b);
    return *(unsigned*)&h;
}
#define MMA_F16(c, a0, a1, a2, a3, b0, b1)                                    \
    asm volatile("mma.sync.aligned.m16n8k16.row.col.f32.f16.f16.f32 "         \
                 "{%0,%1,%2,%3},{%4,%5,%6,%7},{%8,%9},{%0,%1,%2,%3};"         \
                 : "+f"((c)[0]), "+f"((c)[1]), "+f"((c)[2]), "+f"((c)[3])     \
                 : "r"(a0), "r"(a1), "r"(a2), "r"(a3), "r"(b0), "r"(b1))
#define LDSM4(r0, r1, r2, r3, a)                                              \
    asm volatile("ldmatrix.sync.aligned.m8n8.x4.shared.b16 {%0,%1,%2,%3}, [%4];" \
                 : "=r"(r0), "=r"(r1), "=r"(r2), "=r"(r3) : "r"(a))
#define LDSM4T(r0, r1, r2, r3, a)                                             \
    asm volatile("ldmatrix.sync.aligned.m8n8.x4.trans.shared.b16 {%0,%1,%2,%3}, [%4];" \
                 : "=r"(r0), "=r"(r1), "=r"(r2), "=r"(r3) : "r"(a))
#define CPA(dst, src)                                                         \
    asm volatile("cp.async.cg.shared.global [%0], [%1], 16;"                  \
                 :: "r"(dst), "l"(src))

// ======================= conversion kernels =======================
__global__ __launch_bounds__(256) void wt_kernel(const float* __restrict__ W,
                                                 __half* __restrict__ WT,
                                                 int K, int N) {
    __shared__ float tile[32][33];
    int n0 = blockIdx.x * 32, k0 = blockIdx.y * 32;
    int tx = threadIdx.x & 31, ty = threadIdx.x >> 5;
#pragma unroll
    for (int r = 0; r < 4; r++)
        tile[ty + 8 * r][tx] = W[(long)(k0 + ty + 8 * r) * N + n0 + tx];
    __syncthreads();
#pragma unroll
    for (int r = 0; r < 4; r++)
        WT[(long)(n0 + ty + 8 * r) * K + k0 + tx] =
            __float2half_rn(tile[tx][ty + 8 * r]);
}

__global__ __launch_bounds__(256) void cvt_kernel(const float4* __restrict__ s,
                                                  __half2* __restrict__ d,
                                                  long n4) {
    long i = (long)blockIdx.x * blockDim.x + threadIdx.x;
    long stride = (long)gridDim.x * blockDim.x;
    for (; i < n4; i += stride) {
        float4 v = s[i];
        d[2 * i]     = __floats2half2_rn(v.x, v.y);
        d[2 * i + 1] = __floats2half2_rn(v.z, v.w);
    }
}

// ======================= LN (fp16 out) =======================
__global__ __launch_bounds__(256) void ln_kernel(const float* __restrict__ in,
                                                 __half* __restrict__ out,
                                                 int shift) {
    int row = blockIdx.x;
    int src = (row + shift) & (NTOK - 1);
    const float* p = in + (long)src * CDIM;
    int t = threadIdx.x;
    float v[4], s = 0.f, s2 = 0.f;
#pragma unroll
    for (int i = 0; i < 4; i++) {
        v[i] = p[t + i * 256];
        s += v[i]; s2 += v[i] * v[i];
    }
#pragma unroll
    for (int o = 16; o; o >>= 1) {
        s  += __shfl_xor_sync(~0u, s, o);
        s2 += __shfl_xor_sync(~0u, s2, o);
    }
    __shared__ float red0[8], red1[8];
    int wid = t >> 5, lid = t & 31;
    if (lid == 0) { red0[wid] = s; red1[wid] = s2; }
    __syncthreads();
    if (t < 32) {
        float a = (t < 8) ? red0[t] : 0.f;
        float b = (t < 8) ? red1[t] : 0.f;
#pragma unroll
        for (int o = 4; o; o >>= 1) {
            a += __shfl_xor_sync(~0u, a, o);
            b += __shfl_xor_sync(~0u, b, o);
        }
        if (t == 0) { red0[0] = a; red1[0] = b; }
    }
    __syncthreads();
    float mean = red0[0] * (1.f / CDIM);
    float var  = red1[0] * (1.f / CDIM) - mean * mean;
    float r = rsqrtf(var + 1e-6f);
    __half* q = out + (long)row * CDIM;
#pragma unroll
    for (int i = 0; i < 4; i++)
        q[t + i * 256] = __float2half_rn((v[i] - mean) * r);
}

// ======================= gemm_a =======================
#define SROWH 40
#define ABYTES (128 * SROWH * 2)
#define STAGEB (2 * ABYTES)
#define SMEMA (3 * STAGEB)

__global__ __launch_bounds__(256, 2) void gemm_a(
    const __half* __restrict__ A0, const __half* __restrict__ A1,
    const __half* __restrict__ A2, int kb1, int kb2,
    int lda0, int lda1, int lda2,
    const __half* __restrict__ Bt, int ldb,
    float* __restrict__ C, __half* __restrict__ Ch, int ldc,
    const float* __restrict__ bias, const float* __restrict__ resid,
    int K, int epi, int rowShift, int bandw)
{
    extern __shared__ __half dsm[];
    const uint32_t sb0 = smem_u32(dsm);

    int gx = gridDim.x, gy = gridDim.y;
    int id = blockIdx.y * gx + blockIdx.x;
    int per = bandw * gy;
    int band = id / per, rem = id - band * per;
    int bx = band * bandw + (rem % bandw);
    int by = rem / bandw;
    const int m0 = by * 128, n0 = bx * 128;

    const int tid = threadIdx.x, lane = tid & 31, wid = tid >> 5;
    const int wm = wid >> 2, wn = wid & 3;
    const int g = lane >> 2, t4 = lane & 3;

    float acc[4][4][4];
#pragma unroll
    for (int i = 0; i < 4; i++)
#pragma unroll
        for (int j = 0; j < 4; j++)
#pragma unroll
            for (int r = 0; r < 4; r++) acc[i][j][r] = 0.f;

    const int cRow = tid >> 1;
    const int cSeg = tid & 1;
    const uint32_t cOff = (uint32_t)(cRow * SROWH + cSeg * 16) * 2;
    const __half* bSrc = Bt + (long)(n0 + cRow) * ldb + cSeg * 16;

    auto ISSUE = [&](int stage, int k0) {
        uint32_t base = sb0 + stage * STAGEB;
        int gk = k0 + cSeg * 16;
        const __half* ap;
        if (gk < kb1)      ap = A0 + (long)(m0 + cRow) * lda0 + gk;
        else if (gk < kb2) ap = A1 + (long)(m0 + cRow) * lda1 + (gk - kb1);
        else               ap = A2 + (long)(m0 + cRow) * lda2 + (gk - kb2);
        uint32_t ad = base + cOff;
        CPA(ad, ap); CPA(ad + 16, ap + 8);
        uint32_t bd = base + ABYTES + cOff;
        const __half* bp = bSrc + k0;
        CPA(bd, bp); CPA(bd + 16, bp + 8);
        asm volatile("cp.async.commit_group;");
    };

    const int aRowB = (wm * 64 + (lane & 15)) * (SROWH * 2) + (lane >> 4) * 16;
    const int bRowB = (wn * 32 + ((lane >> 4) & 1) * 8 + (lane & 7)) * (SROWH * 2)
                      + ((lane >> 3) & 1) * 16;

    auto COMPUTE = [&](int stage) {
        uint32_t aB = sb0 + stage * STAGEB + aRowB;
        uint32_t bB = sb0 + stage * STAGEB + ABYTES + bRowB;
#pragma unroll
        for (int s = 0; s < 2; s++) {
            uint32_t bw[8];
            LDSM4(bw[0], bw[1], bw[2], bw[3], bB + s * 32);
            LDSM4(bw[4], bw[5], bw[6], bw[7], bB + 16 * (SROWH * 2) + s * 32);
#pragma unroll
            for (int i = 0; i < 4; i++) {
                uint32_t aw[4];
                LDSM4(aw[0], aw[1], aw[2], aw[3],
                      aB + i * 16 * (SROWH * 2) + s * 32);
#pragma unroll
                for (int j = 0; j < 4; j++)
                    MMA_F16(acc[i][j], aw[0], aw[1], aw[2], aw[3],
                            bw[2 * j], bw[2 * j + 1]);
            }
        }
    };

    const int T = K / 32;
    ISSUE(0, 0);
    ISSUE(1, 32);
    for (int t = 0; t < T; t++) {
        if (t + 2 <= T) asm volatile("cp.async.wait_group 1;" ::: "memory");
        else            asm volatile("cp.async.wait_group 0;" ::: "memory");
        __syncthreads();
        if (t + 2 < T) ISSUE((t + 2) % 3, (t + 2) * 32);
        COMPUTE(t % 3);
    }

#pragma unroll
    for (int i = 0; i < 4; i++) {
        int mr = m0 + wm * 64 + i * 16 + g;
        int r0 = rowShift ? ((mr + rowShift) & (NTOK - 1)) : mr;
        int r1 = rowShift ? ((mr + 8 + rowShift) & (NTOK - 1)) : (mr + 8);
#pragma unroll
        for (int j = 0; j < 4; j++) {
            int col = n0 + wn * 32 + j * 8 + (t4 << 1);
            float b0 = bias[col], b1 = bias[col + 1];
            float v00 = acc[i][j][0] + b0;
            float v01 = acc[i][j][1] + b1;
            float v10 = acc[i][j][2] + b0;
            float v11 = acc[i][j][3] + b1;
            if (epi == 1) {
                *(__half2*)(Ch + (long)r0 * ldc + col) =
                    __floats2half2_rn(gelu_tanh(v00), gelu_tanh(v01));
                *(__half2*)(Ch + (long)r1 * ldc + col) =
                    __floats2half2_rn(gelu_tanh(v10), gelu_tanh(v11));
            } else if (epi == 3) {
                *(__half2*)(Ch + (long)r0 * ldc + col) = __floats2half2_rn(v00, v01);
                *(__half2*)(Ch + (long)r1 * ldc + col) = __floats2half2_rn(v10, v11);
            } else {
                if (epi == 2) {
                    const float* q0 = resid + (long)r0 * ldc + col;
                    const float* q1 = resid + (long)r1 * ldc + col;
                    v00 += q0[0]; v01 += q0[1];
                    v10 += q1[0]; v11 += q1[1];
                }
                *(float2*)(C + (long)r0 * ldc + col) = make_float2(v00, v01);
                *(float2*)(C + (long)r1 * ldc + col) = make_float2(v10, v11);
            }
        }
    }
}

// ======================= fused flash attention (2-stage) =================
#define AROWB 144
#define QTILE (128 * AROWB)            // 18432 B
#define KVSTG (2 * QTILE)              // 36864 B
#define SMEMF (QTILE + 2 * KVSTG)      // 92160 B -> 2 CTAs/SM

__global__ __launch_bounds__(256) void attn_fused(
    const __half* __restrict__ qkvh, __half* __restrict__ attnh)
{
    extern __shared__ char fsm[];
    const uint32_t sb = smem_u32(fsm);

    const int tid = threadIdx.x, lane = tid & 31, wid = tid >> 5;
    const int g = lane >> 2, t4 = lane & 3;
    const int z = blockIdx.y, w = z >> 4, hh = z & 15;
    const int m0 = blockIdx.x * 128;

    const __half* Qg = qkvh + ((long)(w * WS + m0)) * (3 * CDIM) + hh * HDIM;
    const __half* Kg = qkvh + ((long)(w * WS)) * (3 * CDIM) + CDIM + hh * HDIM;
    const __half* Vg = Kg + CDIM;

    const int cRow = tid >> 1, cSeg = tid & 1;
    const uint32_t cOff = (uint32_t)(cRow * AROWB + cSeg * 64);

    auto ISSUE_Q = [&]() {
        uint32_t d = sb + cOff;
        const __half* s = Qg + (long)cRow * (3 * CDIM) + cSeg * 32;
        CPA(d, s); CPA(d + 16, s + 8); CPA(d + 32, s + 16); CPA(d + 48, s + 24);
    };
    auto ISSUE_KV = [&](int stage, int t) {
        uint32_t kb = sb + QTILE + stage * KVSTG + cOff;
        long tok = (long)(t * 128 + cRow) * (3 * CDIM);
        const __half* ks = Kg + tok + cSeg * 32;
        const __half* vs = Vg + tok + cSeg * 32;
        CPA(kb, ks); CPA(kb + 16, ks + 8); CPA(kb + 32, ks + 16); CPA(kb + 48, ks + 24);
        uint32_t vb = kb + QTILE;
        CPA(vb, vs); CPA(vb + 16, vs + 8); CPA(vb + 32, vs + 16); CPA(vb + 48, vs + 24);
        asm volatile("cp.async.commit_group;");
    };

    const uint32_t qB = sb + (wid * 16 + (lane & 15)) * AROWB + (lane >> 4) * 16;
    const uint32_t kOffB = (((lane >> 4) & 1) * 8 + (lane & 7)) * AROWB
                           + ((lane >> 3) & 1) * 16;
    const uint32_t vOffB = (lane & 15) * AROWB + (lane >> 4) * 16;

    uint32_t qa[4][4];
    float od[8][4];
#pragma unroll
    for (int j = 0; j < 8; j++)
#pragma unroll
        for (int r = 0; r < 4; r++) od[j][r] = 0.f;
    float rmA = -1e30f, rmB = -1e30f, rsA = 0.f, rsB = 0.f;

    ISSUE_Q();
    ISSUE_KV(0, 0);          // group 0 (Q + KV0)
    ISSUE_KV(1, 1);          // group 1

    for (int t = 0; t < 4; t++) {
        if (t < 3) asm volatile("cp.async.wait_group 1;" ::: "memory");
        else       asm volatile("cp.async.wait_group 0;" ::: "memory");
        __syncthreads();
        if (t == 0) {
#pragma unroll
            for (int s = 0; s < 4; s++)
                LDSM4(qa[s][0], qa[s][1], qa[s][2], qa[s][3], qB + s * 32);
        }

        const uint32_t Kb = sb + QTILE + (t & 1) * KVSTG;
        const uint32_t Vb = Kb + QTILE;

        // ---- QK: S[16 x 128] ----
        float sv[16][4];
#pragma unroll
        for (int j = 0; j < 16; j++)
#pragma unroll
            for (int r = 0; r < 4; r++) sv[j][r] = 0.f;
#pragma unroll
        for (int s = 0; s < 4; s++) {
#pragma unroll
            for (int p = 0; p < 8; p++) {
                uint32_t kb[4];
                LDSM4(kb[0], kb[1], kb[2], kb[3],
                      Kb + kOffB + p * (16 * AROWB) + s * 32);
                MMA_F16(sv[2 * p],     qa[s][0], qa[s][1], qa[s][2], qa[s][3],
                        kb[0], kb[1]);
                MMA_F16(sv[2 * p + 1], qa[s][0], qa[s][1], qa[s][2], qa[s][3],
                        kb[2], kb[3]);
            }
        }

        // ---- online softmax ----
        float mA = -1e30f, mB = -1e30f;
#pragma unroll
        for (int j = 0; j < 16; j++) {
            sv[j][0] *= 0.125f; sv[j][1] *= 0.125f;
            sv[j][2] *= 0.125f; sv[j][3] *= 0.125f;
            mA = fmaxf(mA, fmaxf(sv[j][0], sv[j][1]));
            mB = fmaxf(mB, fmaxf(sv[j][2], sv[j][3]));
        }
        mA = fmaxf(mA, __shfl_xor_sync(~0u, mA, 1));
        mA = fmaxf(mA, __shfl_xor_sync(~0u, mA, 2));
        mB = fmaxf(mB, __shfl_xor_sync(~0u, mB, 1));
        mB = fmaxf(mB, __shfl_xor_sync(~0u, mB, 2));
        float nmA = fmaxf(rmA, mA), nmB = fmaxf(rmB, mB);
        float scA = __expf(rmA - nmA), scB = __expf(rmB - nmB);
        float sA = 0.f, sB = 0.f;
#pragma unroll
        for (int j = 0; j < 16; j++) {
            sv[j][0] = __expf(sv[j][0] - nmA);
            sv[j][1] = __expf(sv[j][1] - nmA);
            sv[j][2] = __expf(sv[j][2] - nmB);
            sv[j][3] = __expf(sv[j][3] - nmB);
            sA += sv[j][0] + sv[j][1];
            sB += sv[j][2] + sv[j][3];
        }
        sA += __shfl_xor_sync(~0u, sA, 1);
        sA += __shfl_xor_sync(~0u, sA, 2);
        sB += __shfl_xor_sync(~0u, sB, 1);
        sB += __shfl_xor_sync(~0u, sB, 2);
        rsA = rsA * scA + sA;
        rsB = rsB * scB + sB;
        rmA = nmA; rmB = nmB;
#pragma unroll
        for (int j = 0; j < 8; j++) {
            od[j][0] *= scA; od[j][1] *= scA;
            od[j][2] *= scB; od[j][3] *= scB;
        }

        // ---- PV ----
#pragma unroll
        for (int sp = 0; sp < 8; sp++) {
            unsigned a0 = h2(sv[2 * sp][0],     sv[2 * sp][1]);
            unsigned a1 = h2(sv[2 * sp][2],     sv[2 * sp][3]);
            unsigned a2 = h2(sv[2 * sp + 1][0], sv[2 * sp + 1][1]);
            unsigned a3 = h2(sv[2 * sp + 1][2], sv[2 * sp + 1][3]);
#pragma unroll
            for (int q = 0; q < 4; q++) {
                uint32_t vb[4];
                LDSM4T(vb[0], vb[1], vb[2], vb[3],
                       Vb + vOffB + sp * (16 * AROWB) + q * 32);
                MMA_F16(od[2 * q],     a0, a1, a2, a3, vb[0], vb[1]);
                MMA_F16(od[2 * q + 1], a0, a1, a2, a3, vb[2], vb[3]);
            }
        }
        __syncthreads();
        if (t + 2 < 4) ISSUE_KV(t & 1, t + 2);   // reuse the buffer just read
    }

    // ---- epilogue ----
    float invA = __frcp_rn(rsA), invB = __frcp_rn(rsB);
    long rowA = ((long)(w * WS + m0 + wid * 16 + g)) * CDIM + hh * HDIM;
    long rowB = rowA + 8L * CDIM;
#pragma unroll
    for (int j = 0; j < 8; j++) {
        int col = j * 8 + (t4 << 1);
        *(__half2*)(attnh + rowA + col) =
            __floats2half2_rn(od[j][0] * invA, od[j][1] * invA);
        *(__half2*)(attnh + rowB + col) =
            __floats2half2_rn(od[j][2] * invB, od[j][3] * invB);
    }
}

// ======================= launch =======================
extern "C" void kernel_launch(void* const* d_in, const int* in_sizes, int n_in,
                              void* d_out, int out_size) {
    const float* x      = (const float*)d_in[0];
    const float* mvn    = (const float*)d_in[1];
    const float* mvc    = (const float*)d_in[2];
    const float* qkv_w  = (const float*)d_in[3];
    const float* qkv_b  = (const float*)d_in[4];
    const float* proj_w = (const float*)d_in[5];
    const float* proj_b = (const float*)d_in[6];
    const float* mv_w1  = (const float*)d_in[7];
    const float* mv_b1  = (const float*)d_in[8];
    const float* mv_w2  = (const float*)d_in[9];
    const float* mv_b2  = (const float*)d_in[10];
    const float* mlp_w1 = (const float*)d_in[11];
    const float* mlp_b1 = (const float*)d_in[12];
    const float* mlp_w2 = (const float*)d_in[13];
    const float* mlp_b2 = (const float*)d_in[14];
    float* out = (float*)d_out;

    float *x1, *x2;
    __half *qkvh, *qkvwT, *projwT, *mv1T, *mv2T, *mlp1T, *mlp2T;
    __half *mvnh, *mvch, *lnxh, *lnbh, *h1h, *attnh;
    cudaGetSymbolAddress((void**)&x1,     g_x1);
    cudaGetSymbolAddress((void**)&x2,     g_x2);
    cudaGetSymbolAddress((void**)&qkvh,   g_qkvh);
    cudaGetSymbolAddress((void**)&qkvwT,  g_qkvwT);
    cudaGetSymbolAddress((void**)&projwT, g_projwT);
    cudaGetSymbolAddress((void**)&mv1T,   g_mv1T);
    cudaGetSymbolAddress((void**)&mv2T,   g_mv2T);
    cudaGetSymbolAddress((void**)&mlp1T,  g_mlp1T);
    cudaGetSymbolAddress((void**)&mlp2T,  g_mlp2T);
    cudaGetSymbolAddress((void**)&mvnh,   g_mvnh);
    cudaGetSymbolAddress((void**)&mvch,   g_mvch);
    cudaGetSymbolAddress((void**)&lnxh,   g_lnxh);
    cudaGetSymbolAddress((void**)&lnbh,   g_lnbh);
    cudaGetSymbolAddress((void**)&h1h,    g_h1h);
    cudaGetSymbolAddress((void**)&attnh,  g_attnh);

    cudaFuncSetAttribute(gemm_a, cudaFuncAttributeMaxDynamicSharedMemorySize, SMEMA);
    cudaFuncSetAttribute(attn_fused, cudaFuncAttributeMaxDynamicSharedMemorySize, SMEMF);

    // 0) pre-convert weights (transposed) and mv tensors to fp16
    wt_kernel<<<dim3(3 * CDIM / 32, CDIM / 32), 256>>>(qkv_w, qkvwT, CDIM, 3 * CDIM);
    wt_kernel<<<dim3(CDIM / 32, CDIM / 32), 256>>>(proj_w, projwT, CDIM, CDIM);
    wt_kernel<<<dim3(HID / 32, KCAT / 32), 256>>>(mv_w1, mv1T, KCAT, HID);
    wt_kernel<<<dim3(CDIM / 32, HID / 32), 256>>>(mv_w2, mv2T, HID, CDIM);
    wt_kernel<<<dim3(HID / 32, CDIM / 32), 256>>>(mlp_w1, mlp1T, CDIM, HID);
    wt_kernel<<<dim3(CDIM / 32, HID / 32), 256>>>(mlp_w2, mlp2T, HID, CDIM);
    long n4 = (long)NTOK * MVD4 / 4;
    cvt_kernel<<<8192, 256>>>((const float4*)mvn, (__half2*)mvnh, n4);
    cvt_kernel<<<8192, 256>>>((const float4*)mvc, (__half2*)mvch, n4);

    // 1) lnx_h[j] = LN(x[(j+SHIFT)%N])
    ln_kernel<<<NTOK, 256>>>(x, lnxh, SHIFTK);

    // 2) qkv_h = lnxh @ qkvwT^T + qkv_b   (fp16 out)
    gemm_a<<<dim3(3 * CDIM / 128, NTOK / 128), 256, SMEMA>>>(
        lnxh, nullptr, nullptr, CDIM, CDIM, CDIM, 0, 0,
        qkvwT, CDIM, nullptr, qkvh, 3 * CDIM, qkv_b, nullptr,
        CDIM, 3, 0, 24);

    // 3-5) fused attention
    attn_fused<<<dim3(4, NZ), 256, SMEMF>>>(qkvh, attnh);

    // 6) x1[(m+SHIFT)%N] = x[...] + attnh@projwT^T + proj_b
    gemm_a<<<dim3(CDIM / 128, NTOK / 128), 256, SMEMA>>>(
        attnh, nullptr, nullptr, CDIM, CDIM, CDIM, 0, 0,
        projwT, CDIM, x1, nullptr, CDIM, proj_b, x,
        CDIM, 2, SHIFTK, 8);

    // 7) mv branch
    ln_kernel<<<NTOK, 256>>>(x1, lnbh, 0);
    gemm_a<<<dim3(HID / 128, NTOK / 128), 256, SMEMA>>>(
        lnbh, mvnh, mvch, CDIM, CDIM + MVD4, CDIM, MVD4, MVD4,
        mv1T, KCAT, nullptr, h1h, HID, mv_b1, nullptr,
        KCAT, 1, 0, 32);
    gemm_a<<<dim3(CDIM / 128, NTOK / 128), 256, SMEMA>>>(
        h1h, nullptr, nullptr, HID, HID, HID, 0, 0,
        mv2T, HID, x2, nullptr, CDIM, mv_b2, x1,
        HID, 2, 0, 8);

    // 8) mlp branch
    ln_kernel<<<NTOK, 256>>>(x2, lnbh, 0);
    gemm_a<<<dim3(HID / 128, NTOK / 128), 256, SMEMA>>>(
        lnbh, nullptr, nullptr, CDIM, CDIM, CDIM, 0, 0,
        mlp1T, CDIM, nullptr, h1h, HID, mlp_b1, nullptr,
        CDIM, 1, 0, 32);
    gemm_a<<<dim3(CDIM / 128, NTOK / 128), 256, SMEMA>>>(
        h1h, nullptr, nullptr, HID, HID, HID, 0, 0,
        mlp2T, HID, out, nullptr, CDIM, mlp_b2, x2,
        HID, 2, 0, 8);
}